// round 2
// baseline (speedup 1.0000x reference)
#include <cuda_runtime.h>
#include <cstdint>
#include <cstddef>

#define NB 8
#define NN 256
#define NH 64
#define NL 2
#define NA 10
#define LN_EPS 1e-5f

// SMEM row strides (floats). 68 = 16B-aligned rows AND conflict-free float4 access
// (phase of 8 lanes -> start banks 0,4,8,...,28 each spanning 4 banks = all 32).
#define EST 68
#define W4ST 68

#define SMEM_MAIN_FLOATS (NN*EST + NH*W4ST + NH + NN + NH + NH + 16)
#define SMEM_MAIN_BYTES (SMEM_MAIN_FLOATS * 4)

// ---------------- device scratch (no allocations allowed) ----------------
__device__ float g_E1[(size_t)NB*NN*NN*NH];   // 128 MB inter-layer E buffer
__device__ float g_Xbuf[NB*NN*NH];
__device__ float g_XJ[NB*NN*NH];              // X @ W5^T
__device__ float g_XR[NB*NN*NH];              // X @ W6^T
__device__ float g_AGG[NB*NN*NH];             // einsum result
__device__ float g_S[NB*NN];                  // row sums of Xi
__device__ float g_w3s[NL*NH];
__device__ float g_w4s[NL*NH];

// ---------------- f32x2 helpers ----------------
#define FMA2(acc, a, b) asm("fma.rn.f32x2 %0, %1, %2, %0;" : "+l"(acc) : "l"(a), "l"(b))

__device__ __forceinline__ unsigned long long pack2(float lo, float hi) {
    unsigned long long r;
    asm("mov.b64 %0, {%1, %2};" : "=l"(r) : "f"(lo), "f"(hi));
    return r;
}
__device__ __forceinline__ void unpack2(unsigned long long v, float& lo, float& hi) {
    asm("mov.b64 {%0, %1}, %2;" : "=f"(lo), "=f"(hi) : "l"(v));
}

// ---------------- tiny precompute: column sums of W3 / W4 ----------------
__global__ void k_sums(const float* __restrict__ W3, const float* __restrict__ W4) {
    int t = threadIdx.x;            // 128 threads: (layer, k)
    int l = t >> 6, k = t & 63;
    float s3 = 0.f, s4 = 0.f;
    #pragma unroll 8
    for (int h = 0; h < NH; h++) {
        s3 += W3[(l*NH + h)*NH + k];
        s4 += W4[(l*NH + h)*NH + k];
    }
    g_w3s[t] = s3;
    g_w4s[t] = s4;
}

// ---------------- per-row X-path pre: s, Xj=X@W5^T, Xres=X@W6^T ----------------
__global__ void k_xpre(const float* __restrict__ X0, const float* __restrict__ W5,
                       const float* __restrict__ W6, int layer) {
    __shared__ float Xs[NH];
    __shared__ float W5T[NH*65];
    __shared__ float W6T[NH*65];
    __shared__ float red[2];
    const float* Xin  = layer ? g_Xbuf : X0;
    const float* W5l  = W5 + layer*NH*NH;
    const float* W6l  = W6 + layer*NH*NH;
    const float* w3sl = g_w3s + layer*NH;

    int row = blockIdx.x, h = threadIdx.x;
    Xs[h] = Xin[row*NH + h];
    for (int idx = h; idx < NH*NH; idx += NH) {
        int r = idx >> 6, k = idx & 63;
        W5T[k*65 + r] = W5l[idx];
        W6T[k*65 + r] = W6l[idx];
    }
    __syncthreads();

    float a5 = 0.f, a6 = 0.f;
    #pragma unroll 8
    for (int k = 0; k < NH; k++) {
        float x = Xs[k];
        a5 = fmaf(x, W5T[k*65 + h], a5);
        a6 = fmaf(x, W6T[k*65 + h], a6);
    }
    g_XJ[row*NH + h] = a5;
    g_XR[row*NH + h] = a6;

    float p = Xs[h] * w3sl[h];
    #pragma unroll
    for (int o = 16; o; o >>= 1) p += __shfl_xor_sync(0xffffffffu, p, o);
    if ((h & 31) == 0) red[h >> 5] = p;
    __syncthreads();
    if (h == 0) g_S[row] = red[0] + red[1];
}

// ---------------- main fused kernel: one block per (b,i) row-slab of E ----------------
// logits (exact via w4sum dot) -> block softmax -> f32x2 GEMM E_hat = E @ W4^T
// -> E_next = att*E_hat -> agg reduction (with Xj) -> LayerNorm + E1 write (layer 0 only)
__global__ void __launch_bounds__(256, 2) k_main(
    const float* __restrict__ E0, const float* __restrict__ W4,
    const float* __restrict__ eg, const float* __restrict__ eb, int layer) {
    extern __shared__ float sm[];
    float* Es   = sm;                    // [256][EST]
    float* W4T  = Es + NN*EST;           // [64][W4ST], W4T[k][h] = W4[h][k]
    float* w4s  = W4T + NH*W4ST;         // [64]
    float* sAll = w4s + NH;              // [256] (reused as agg partials)
    float* egs  = sAll + NN;             // [64]
    float* ebs  = egs + NH;              // [64]
    float* red  = ebs + NH;              // [16]

    const float* Ein  = layer ? g_E1 : E0;
    const float* W4l  = W4 + layer*NH*NH;
    const float* w4sl = g_w4s + layer*NH;

    const int bi = blockIdx.x;
    const int b  = bi >> 8;
    const int t  = threadIdx.x;

    // --- load 64KB E slab (contiguous for this (b,i)) into SMEM, float4 ---
    const float4* Eg4 = reinterpret_cast<const float4*>(Ein + (size_t)bi*NN*NH);
    #pragma unroll
    for (int c = 0; c < 16; c++) {
        int idx4 = t + NN*c;
        int j = idx4 >> 4, k4 = idx4 & 15;
        reinterpret_cast<float4*>(Es + j*EST)[k4] = Eg4[idx4];
    }
    // --- W4 transposed into SMEM ---
    for (int idx = t; idx < NH*NH; idx += 256) {
        int h = idx >> 6, k = idx & 63;
        W4T[k*W4ST + h] = W4l[idx];
    }
    if (t < NH) {
        w4s[t] = w4sl[t];
        egs[t] = eg[layer*NH + t];
        ebs[t] = eb[layer*NH + t];
    }
    sAll[t] = g_S[b*NN + t];
    __syncthreads();

    const int j = t;  // one row per thread
    const float4* er4 = reinterpret_cast<const float4*>(Es + j*EST);

    // --- exact logits: E[b,i,j,:] . w4sum + s_i + s_j ---
    float lg = 0.f;
    const float4* ws4 = reinterpret_cast<const float4*>(w4s);
    #pragma unroll
    for (int c = 0; c < 16; c++) {
        float4 e = er4[c]; float4 w = ws4[c];
        lg += e.x*w.x + e.y*w.y + e.z*w.z + e.w*w.w;
    }
    lg += g_S[bi] + sAll[j];

    // --- block softmax over 256 ---
    float m = lg;
    #pragma unroll
    for (int o = 16; o; o >>= 1) m = fmaxf(m, __shfl_xor_sync(0xffffffffu, m, o));
    if ((t & 31) == 0) red[t >> 5] = m;
    __syncthreads();
    if (t == 0) {
        float mm = red[0];
        for (int w = 1; w < 8; w++) mm = fmaxf(mm, red[w]);
        red[8] = mm;
    }
    __syncthreads();
    m = red[8];
    float ex = expf(lg - m);
    float sum = ex;
    #pragma unroll
    for (int o = 16; o; o >>= 1) sum += __shfl_xor_sync(0xffffffffu, sum, o);
    if ((t & 31) == 0) red[t >> 5] = sum;
    __syncthreads();
    if (t == 0) {
        float s8 = 0.f;
        for (int w = 0; w < 8; w++) s8 += red[w];
        red[9] = 1.f / s8;
    }
    __syncthreads();
    const float att = ex * red[9];

    // --- f32x2 GEMM: E_hat[j,h] = sum_k E[j,k] * W4T[k,h], acc pairs (2h, 2h+1) ---
    unsigned long long acc2[32];
    #pragma unroll
    for (int q = 0; q < 32; q++) acc2[q] = 0ull;

    for (int kc = 0; kc < 16; kc++) {
        float4 ev = er4[kc];
        float es4[4] = {ev.x, ev.y, ev.z, ev.w};
        #pragma unroll
        for (int kk = 0; kk < 4; kk++) {
            unsigned long long e2 = pack2(es4[kk], es4[kk]);
            const ulonglong2* wr =
                reinterpret_cast<const ulonglong2*>(W4T + (kc*4 + kk)*W4ST);
            #pragma unroll
            for (int q = 0; q < 16; q++) {
                ulonglong2 wp = wr[q];
                FMA2(acc2[2*q],     e2, wp.x);
                FMA2(acc2[2*q + 1], e2, wp.y);
            }
        }
    }

    // --- E_next = att * E_hat: store to own SMEM row, gather LN stats ---
    float ssum = 0.f, ssq = 0.f;
    float* enrow = Es + j*EST;
    #pragma unroll
    for (int q = 0; q < 16; q++) {
        float a0, a1, a2, a3;
        unpack2(acc2[2*q],     a0, a1);
        unpack2(acc2[2*q + 1], a2, a3);
        a0 *= att; a1 *= att; a2 *= att; a3 *= att;
        float4 v = {a0, a1, a2, a3};
        reinterpret_cast<float4*>(enrow)[q] = v;
        ssum += (a0 + a1) + (a2 + a3);
        ssq  += a0*a0 + a1*a1 + a2*a2 + a3*a3;
    }
    __syncthreads();

    // --- agg[h] = sum_j E_next[j,h] * Xj[b,j,h] ---
    {
        int h = t & 63, jc = t >> 6;
        const float* XJb = g_XJ + (size_t)b*NN*NH;
        float pa = 0.f;
        #pragma unroll 4
        for (int jj = 0; jj < 64; jj++) {
            int jr = (jc << 6) + jj;
            pa = fmaf(Es[jr*EST + h], XJb[jr*NH + h], pa);
        }
        sAll[t] = pa;
    }
    __syncthreads();
    if (t < NH)
        g_AGG[bi*NH + t] = sAll[t] + sAll[NH + t] + sAll[2*NH + t] + sAll[3*NH + t];

    // --- layer 0 only: E1 = LayerNorm(E_next), coalesced write-out ---
    if (layer == 0) {
        float mean = ssum * (1.f/NH);
        float var  = fmaf(ssq, 1.f/NH, -mean*mean);
        float rstd = rsqrtf(var + LN_EPS);
        __syncthreads();   // agg phase must finish reading Es before overwrite
        #pragma unroll
        for (int q = 0; q < 16; q++) {
            float a0, a1, a2, a3;
            unpack2(acc2[2*q],     a0, a1);
            unpack2(acc2[2*q + 1], a2, a3);
            int hb = 4*q;
            a0 = (att*a0 - mean)*rstd*egs[hb+0] + ebs[hb+0];
            a1 = (att*a1 - mean)*rstd*egs[hb+1] + ebs[hb+1];
            a2 = (att*a2 - mean)*rstd*egs[hb+2] + ebs[hb+2];
            a3 = (att*a3 - mean)*rstd*egs[hb+3] + ebs[hb+3];
            float4 v = {a0, a1, a2, a3};
            reinterpret_cast<float4*>(enrow)[q] = v;
        }
        __syncthreads();
        float4* Eo4 = reinterpret_cast<float4*>(g_E1 + (size_t)bi*NN*NH);
        #pragma unroll
        for (int c = 0; c < 16; c++) {
            int idx4 = t + NN*c;
            int jr = idx4 >> 4, k4 = idx4 & 15;
            Eo4[idx4] = reinterpret_cast<const float4*>(Es + jr*EST)[k4];
        }
    }
}

// ---------------- X update: X = LN(relu(agg + Xres)) + X ----------------
__global__ void k_xpost(const float* __restrict__ X0, const float* __restrict__ ng,
                        const float* __restrict__ nb, int layer) {
    __shared__ float red[2];
    __shared__ float bc[2];
    const float* Xin = layer ? g_Xbuf : X0;
    int row = blockIdx.x, h = threadIdx.x;

    float v = g_AGG[row*NH + h] + g_XR[row*NH + h];
    v = fmaxf(v, 0.f);

    float p = v;
    #pragma unroll
    for (int o = 16; o; o >>= 1) p += __shfl_xor_sync(0xffffffffu, p, o);
    if ((h & 31) == 0) red[h >> 5] = p;
    __syncthreads();
    if (h == 0) bc[0] = (red[0] + red[1]) * (1.f/NH);
    __syncthreads();
    float mean = bc[0];
    float d = v - mean;
    p = d*d;
    #pragma unroll
    for (int o = 16; o; o >>= 1) p += __shfl_xor_sync(0xffffffffu, p, o);
    if ((h & 31) == 0) red[h >> 5] = p;
    __syncthreads();
    if (h == 0) bc[1] = rsqrtf((red[0] + red[1]) * (1.f/NH) + LN_EPS);
    __syncthreads();

    float out = d * bc[1] * ng[layer*NH + h] + nb[layer*NH + h] + Xin[row*NH + h];
    g_Xbuf[row*NH + h] = out;
}

// ---------------- head: out = relu(X@hw1^T + hb1) @ hw2^T + hb2 ----------------
__global__ void k_head(const float* __restrict__ hw1, const float* __restrict__ hb1,
                       const float* __restrict__ hw2, const float* __restrict__ hb2,
                       float* __restrict__ out) {
    __shared__ float Xs[NH];
    __shared__ float W1T[NH*65];
    __shared__ float h1[NH];
    int row = blockIdx.x, h = threadIdx.x;
    Xs[h] = g_Xbuf[row*NH + h];
    for (int idx = h; idx < NH*NH; idx += NH) {
        int r = idx >> 6, k = idx & 63;
        W1T[k*65 + r] = hw1[idx];
    }
    __syncthreads();
    float a = hb1[h];
    #pragma unroll 8
    for (int k = 0; k < NH; k++) a = fmaf(Xs[k], W1T[k*65 + h], a);
    h1[h] = fmaxf(a, 0.f);
    __syncthreads();
    if (h < NA) {
        float o = hb2[h];
        #pragma unroll 8
        for (int k = 0; k < NH; k++) o = fmaf(h1[k], hw2[h*NH + k], o);
        out[row*NA + h] = o;
    }
}

// ---------------- launch ----------------
extern "C" void kernel_launch(void* const* d_in, const int* in_sizes, int n_in,
                              void* d_out, int out_size) {
    const float* X   = (const float*)d_in[0];
    const float* E   = (const float*)d_in[1];
    const float* W3  = (const float*)d_in[2];
    const float* W4  = (const float*)d_in[3];
    const float* W5  = (const float*)d_in[4];
    const float* W6  = (const float*)d_in[5];
    const float* ng  = (const float*)d_in[6];
    const float* nb  = (const float*)d_in[7];
    const float* eg  = (const float*)d_in[8];
    const float* eb  = (const float*)d_in[9];
    const float* hw1 = (const float*)d_in[10];
    const float* hb1 = (const float*)d_in[11];
    const float* hw2 = (const float*)d_in[12];
    const float* hb2 = (const float*)d_in[13];
    float* out = (float*)d_out;

    // idempotent; persists across the correctness call so capture-time launches are valid
    cudaFuncSetAttribute(k_main, cudaFuncAttributeMaxDynamicSharedMemorySize,
                         SMEM_MAIN_BYTES);

    k_sums<<<1, 128>>>(W3, W4);
    for (int l = 0; l < NL; l++) {
        k_xpre<<<NB*NN, NH>>>(X, W5, W6, l);
        k_main<<<NB*NN, NN, SMEM_MAIN_BYTES>>>(E, W4, eg, eb, l);
        k_xpost<<<NB*NN, NH>>>(X, ng, nb, l);
    }
    k_head<<<NB*NN, NH>>>(hw1, hb1, hw2, hb2, out);
}

// round 4
// speedup vs baseline: 1.4493x; 1.4493x over previous
#include <cuda_runtime.h>
#include <cstdint>
#include <cstddef>

#define NB 8
#define NN 256
#define NH 64
#define NL 2
#define NA 10
#define LN_EPS 1e-5f

// SMEM strides (floats)
#define EST 68      // E rows: 16B-aligned, conflict-free for frag loads (gid*4+tig)
#define W4ST 72     // W4T rows: tig*72 mod 32 = {0,8,16,24} -> conflict-free B frags

// SMEM word offsets
#define O_ES    0
#define O_W4T   17408           // 256*68
#define O_W4S   22016           // +64*72
#define O_SALL  22080
#define O_ATT   22336
#define O_SUM   22592
#define O_SQ    22848
#define O_RED   23104
#define O_EG    23120
#define O_EB    23184
#define SMEM_MAIN_WORDS 23248
#define SMEM_MAIN_BYTES (SMEM_MAIN_WORDS * 4)

// ---------------- device scratch ----------------
__device__ float g_E1[(size_t)NB*NN*NN*NH];   // 128 MB inter-layer E buffer
__device__ float g_Xbuf[NB*NN*NH];
__device__ float g_XJ[NB*NN*NH];              // X @ W5^T
__device__ float g_XR[NB*NN*NH];              // X @ W6^T
__device__ float g_AGG[NB*NN*NH];             // einsum result
__device__ float g_S[NB*NN];                  // row sums of Xi
__device__ float g_w3s[NL*NH];
__device__ float g_w4s[NL*NH];

// ---------------- tf32 mma.sync helpers ----------------
__device__ __forceinline__ uint32_t tf32b(float x) {
    float r;
    asm("cvt.rna.tf32.f32 %0, %1;" : "=f"(r) : "f"(x));
    return __float_as_uint(r);
}

__device__ __forceinline__ void mma_tf32(float* c, const uint32_t* a,
                                         uint32_t b0, uint32_t b1) {
    asm volatile(
        "mma.sync.aligned.m16n8k8.row.col.f32.tf32.tf32.f32 "
        "{%0,%1,%2,%3}, {%4,%5,%6,%7}, {%8,%9}, {%0,%1,%2,%3};"
        : "+f"(c[0]), "+f"(c[1]), "+f"(c[2]), "+f"(c[3])
        : "r"(a[0]), "r"(a[1]), "r"(a[2]), "r"(a[3]), "r"(b0), "r"(b1));
}

// ---------------- tiny precompute: column sums of W3 / W4 ----------------
__global__ void k_sums(const float* __restrict__ W3, const float* __restrict__ W4) {
    int t = threadIdx.x;            // 128 threads: (layer, k)
    int l = t >> 6, k = t & 63;
    float s3 = 0.f, s4 = 0.f;
    #pragma unroll 8
    for (int h = 0; h < NH; h++) {
        s3 += W3[(l*NH + h)*NH + k];
        s4 += W4[(l*NH + h)*NH + k];
    }
    g_w3s[t] = s3;
    g_w4s[t] = s4;
}

// ---------------- per-row X-path pre: s, Xj=X@W5^T, Xres=X@W6^T ----------------
__global__ void k_xpre(const float* __restrict__ X0, const float* __restrict__ W5,
                       const float* __restrict__ W6, int layer) {
    __shared__ float Xs[NH];
    __shared__ float W5T[NH*65];
    __shared__ float W6T[NH*65];
    __shared__ float red[2];
    const float* Xin  = layer ? g_Xbuf : X0;
    const float* W5l  = W5 + layer*NH*NH;
    const float* W6l  = W6 + layer*NH*NH;
    const float* w3sl = g_w3s + layer*NH;

    int row = blockIdx.x, h = threadIdx.x;
    Xs[h] = Xin[row*NH + h];
    for (int idx = h; idx < NH*NH; idx += NH) {
        int r = idx >> 6, k = idx & 63;
        W5T[k*65 + r] = W5l[idx];
        W6T[k*65 + r] = W6l[idx];
    }
    __syncthreads();

    float a5 = 0.f, a6 = 0.f;
    #pragma unroll 8
    for (int k = 0; k < NH; k++) {
        float x = Xs[k];
        a5 = fmaf(x, W5T[k*65 + h], a5);
        a6 = fmaf(x, W6T[k*65 + h], a6);
    }
    g_XJ[row*NH + h] = a5;
    g_XR[row*NH + h] = a6;

    float p = Xs[h] * w3sl[h];
    #pragma unroll
    for (int o = 16; o; o >>= 1) p += __shfl_xor_sync(0xffffffffu, p, o);
    if ((h & 31) == 0) red[h >> 5] = p;
    __syncthreads();
    if (h == 0) g_S[row] = red[0] + red[1];
}

// ---------------- main fused kernel ----------------
// mma.sync tf32 GEMM E_hat = E @ W4^T on the tensor pipe; exact fp32 logits
// via E . w4sum; block softmax; att-scale; LN stats via shfl; agg; E1 write.
__global__ void __launch_bounds__(256, 2) k_main(
    const float* __restrict__ E0, const float* __restrict__ W4,
    const float* __restrict__ eg, const float* __restrict__ eb, int layer) {
    extern __shared__ float sm[];
    float* Es    = sm + O_ES;
    float* W4T   = sm + O_W4T;
    const uint32_t* W4Tu = reinterpret_cast<const uint32_t*>(W4T);
    float* w4s   = sm + O_W4S;
    float* sAll  = sm + O_SALL;
    float* attA  = sm + O_ATT;
    float* sumA  = sm + O_SUM;
    float* sqA   = sm + O_SQ;
    float* red   = sm + O_RED;
    float* egs   = sm + O_EG;
    float* ebs   = sm + O_EB;

    const float* Ein  = layer ? g_E1 : E0;
    const float* W4l  = W4 + layer*NH*NH;
    const float* w4sl = g_w4s + layer*NH;

    const int bi = blockIdx.x;
    const int b  = bi >> 8;
    const int t  = threadIdx.x;
    const int w  = t >> 5;
    const int lane = t & 31;
    const int gid = lane >> 2, tig = lane & 3;

    // --- load 64KB E slab into SMEM (fp32, float4, coalesced) ---
    const float4* Eg4 = reinterpret_cast<const float4*>(Ein + (size_t)bi*NN*NH);
    #pragma unroll
    for (int c = 0; c < 16; c++) {
        int idx4 = t + 256*c;
        int j = idx4 >> 4, k4 = idx4 & 15;
        reinterpret_cast<float4*>(Es + j*EST)[k4] = Eg4[idx4];
    }
    // --- W4 transposed + pre-rounded to tf32 ---
    for (int idx = t; idx < NH*NH; idx += 256) {
        int h = idx >> 6, k = idx & 63;
        W4T[k*W4ST + h] = __uint_as_float(tf32b(W4l[idx]));
    }
    if (t < NH) {
        w4s[t] = w4sl[t];
        egs[t] = eg[layer*NH + t];
        ebs[t] = eb[layer*NH + t];
    }
    sAll[t] = g_S[b*NN + t];
    __syncthreads();

    // --- tensor-pipe GEMM: warp w owns rows [w*32, w*32+32), all 64 cols ---
    float acc[2][8][4];
    #pragma unroll
    for (int mt = 0; mt < 2; mt++)
        #pragma unroll
        for (int nt = 0; nt < 8; nt++)
            #pragma unroll
            for (int q = 0; q < 4; q++) acc[mt][nt][q] = 0.f;

    #pragma unroll
    for (int ks = 0; ks < 8; ks++) {
        const int k0 = ks*8 + tig;
        uint32_t a[2][4];
        #pragma unroll
        for (int mt = 0; mt < 2; mt++) {
            const int r0 = w*32 + mt*16 + gid;
            a[mt][0] = tf32b(Es[r0*EST + k0]);
            a[mt][1] = tf32b(Es[(r0 + 8)*EST + k0]);
            a[mt][2] = tf32b(Es[r0*EST + k0 + 4]);
            a[mt][3] = tf32b(Es[(r0 + 8)*EST + k0 + 4]);
        }
        #pragma unroll
        for (int nt = 0; nt < 8; nt++) {
            uint32_t b0 = W4Tu[k0*W4ST + nt*8 + gid];
            uint32_t b1 = W4Tu[(k0 + 4)*W4ST + nt*8 + gid];
            mma_tf32(acc[0][nt], a[0], b0, b1);
            mma_tf32(acc[1][nt], a[1], b0, b1);
        }
    }

    // --- exact fp32 logits: E[b,i,j,:] . w4sum + s_i + s_j  (row j = t) ---
    float lg = 0.f;
    {
        const float4* er4 = reinterpret_cast<const float4*>(Es + t*EST);
        const float4* ws4 = reinterpret_cast<const float4*>(w4s);
        #pragma unroll
        for (int c = 0; c < 16; c++) {
            float4 e = er4[c]; float4 wv = ws4[c];
            lg += e.x*wv.x + e.y*wv.y + e.z*wv.z + e.w*wv.w;
        }
        lg += g_S[bi] + sAll[t];
    }

    // --- block softmax over 256 ---
    float m = lg;
    #pragma unroll
    for (int o = 16; o; o >>= 1) m = fmaxf(m, __shfl_xor_sync(0xffffffffu, m, o));
    if (lane == 0) red[w] = m;
    __syncthreads();
    if (t == 0) {
        float mm = red[0];
        for (int q = 1; q < 8; q++) mm = fmaxf(mm, red[q]);
        red[8] = mm;
    }
    __syncthreads();
    m = red[8];
    float ex = expf(lg - m);
    float sum = ex;
    #pragma unroll
    for (int o = 16; o; o >>= 1) sum += __shfl_xor_sync(0xffffffffu, sum, o);
    if (lane == 0) red[w] = sum;
    __syncthreads();
    if (t == 0) {
        float s8 = 0.f;
        for (int q = 0; q < 8; q++) s8 += red[q];
        red[9] = 1.f / s8;
    }
    __syncthreads();
    attA[t] = ex * red[9];
    __syncthreads();

    // --- fragment epilogue: scale by att, LN stats, write E_next to Es ---
    #pragma unroll
    for (int mt = 0; mt < 2; mt++) {
        const int rA = w*32 + mt*16 + gid;
        const int rB = rA + 8;
        const float aA = attA[rA], aB = attA[rB];
        float s0 = 0.f, q0 = 0.f, s1 = 0.f, q1 = 0.f;
        #pragma unroll
        for (int nt = 0; nt < 8; nt++) {
            float e0 = acc[mt][nt][0] * aA;
            float e1 = acc[mt][nt][1] * aA;
            float e2 = acc[mt][nt][2] * aB;
            float e3 = acc[mt][nt][3] * aB;
            acc[mt][nt][0] = e0; acc[mt][nt][1] = e1;
            acc[mt][nt][2] = e2; acc[mt][nt][3] = e3;
            s0 += e0 + e1; q0 += e0*e0 + e1*e1;
            s1 += e2 + e3; q1 += e2*e2 + e3*e3;
            const int hc = nt*8 + 2*tig;
            float2 vA = {e0, e1};
            float2 vB = {e2, e3};
            *reinterpret_cast<float2*>(Es + rA*EST + hc) = vA;
            *reinterpret_cast<float2*>(Es + rB*EST + hc) = vB;
        }
        // reduce over the 4-lane tig group
        #pragma unroll
        for (int o = 1; o <= 2; o <<= 1) {
            s0 += __shfl_xor_sync(0xffffffffu, s0, o);
            q0 += __shfl_xor_sync(0xffffffffu, q0, o);
            s1 += __shfl_xor_sync(0xffffffffu, s1, o);
            q1 += __shfl_xor_sync(0xffffffffu, q1, o);
        }
        if (tig == 0) {
            sumA[rA] = s0; sqA[rA] = q0;
            sumA[rB] = s1; sqA[rB] = q1;
        }
    }
    __syncthreads();

    // --- agg[h] = sum_j E_next[j,h] * Xj[b,j,h] ---
    {
        int h = t & 63, jc = t >> 6;
        const float* XJb = g_XJ + (size_t)b*NN*NH;
        float pa = 0.f;
        #pragma unroll 4
        for (int jj = 0; jj < 64; jj++) {
            int jr = (jc << 6) + jj;
            pa = fmaf(Es[jr*EST + h], XJb[jr*NH + h], pa);
        }
        sAll[t] = pa;
    }
    __syncthreads();
    if (t < NH)
        g_AGG[bi*NH + t] = sAll[t] + sAll[NH + t] + sAll[2*NH + t] + sAll[3*NH + t];

    // --- layer 0 only: E1 = LayerNorm(E_next) -> Es -> coalesced write ---
    if (layer == 0) {
        __syncthreads();   // agg reads of Es done before overwrite
        #pragma unroll
        for (int mt = 0; mt < 2; mt++) {
            const int rA = w*32 + mt*16 + gid;
            const int rB = rA + 8;
            const float mA = sumA[rA] * (1.f/NH);
            const float vA = fmaf(sqA[rA], 1.f/NH, -mA*mA);
            const float rsA = rsqrtf(vA + LN_EPS);
            const float mB = sumA[rB] * (1.f/NH);
            const float vB = fmaf(sqA[rB], 1.f/NH, -mB*mB);
            const float rsB = rsqrtf(vB + LN_EPS);
            #pragma unroll
            for (int nt = 0; nt < 8; nt++) {
                const int hc = nt*8 + 2*tig;
                const float g0 = egs[hc], g1 = egs[hc+1];
                const float b0 = ebs[hc], b1 = ebs[hc+1];
                float2 vAo = {(acc[mt][nt][0] - mA)*rsA*g0 + b0,
                              (acc[mt][nt][1] - mA)*rsA*g1 + b1};
                float2 vBo = {(acc[mt][nt][2] - mB)*rsB*g0 + b0,
                              (acc[mt][nt][3] - mB)*rsB*g1 + b1};
                *reinterpret_cast<float2*>(Es + rA*EST + hc) = vAo;
                *reinterpret_cast<float2*>(Es + rB*EST + hc) = vBo;
            }
        }
        __syncthreads();
        float4* Eo4 = reinterpret_cast<float4*>(g_E1 + (size_t)bi*NN*NH);
        #pragma unroll
        for (int c = 0; c < 16; c++) {
            int idx4 = t + 256*c;
            int jr = idx4 >> 4, k4 = idx4 & 15;
            Eo4[idx4] = reinterpret_cast<const float4*>(Es + jr*EST)[k4];
        }
    }
}

// ---------------- X update: X = LN(relu(agg + Xres)) + X ----------------
__global__ void k_xpost(const float* __restrict__ X0, const float* __restrict__ ng,
                        const float* __restrict__ nb, int layer) {
    __shared__ float red[2];
    __shared__ float bc[2];
    const float* Xin = layer ? g_Xbuf : X0;
    int row = blockIdx.x, h = threadIdx.x;

    float v = g_AGG[row*NH + h] + g_XR[row*NH + h];
    v = fmaxf(v, 0.f);

    float p = v;
    #pragma unroll
    for (int o = 16; o; o >>= 1) p += __shfl_xor_sync(0xffffffffu, p, o);
    if ((h & 31) == 0) red[h >> 5] = p;
    __syncthreads();
    if (h == 0) bc[0] = (red[0] + red[1]) * (1.f/NH);
    __syncthreads();
    float mean = bc[0];
    float d = v - mean;
    p = d*d;
    #pragma unroll
    for (int o = 16; o; o >>= 1) p += __shfl_xor_sync(0xffffffffu, p, o);
    if ((h & 31) == 0) red[h >> 5] = p;
    __syncthreads();
    if (h == 0) bc[1] = rsqrtf((red[0] + red[1]) * (1.f/NH) + LN_EPS);
    __syncthreads();

    float out = d * bc[1] * ng[layer*NH + h] + nb[layer*NH + h] + Xin[row*NH + h];
    g_Xbuf[row*NH + h] = out;
}

// ---------------- head: out = relu(X@hw1^T + hb1) @ hw2^T + hb2 ----------------
__global__ void k_head(const float* __restrict__ hw1, const float* __restrict__ hb1,
                       const float* __restrict__ hw2, const float* __restrict__ hb2,
                       float* __restrict__ out) {
    __shared__ float Xs[NH];
    __shared__ float W1T[NH*65];
    __shared__ float h1[NH];
    int row = blockIdx.x, h = threadIdx.x;
    Xs[h] = g_Xbuf[row*NH + h];
    for (int idx = h; idx < NH*NH; idx += NH) {
        int r = idx >> 6, k = idx & 63;
        W1T[k*65 + r] = hw1[idx];
    }
    __syncthreads();
    float a = hb1[h];
    #pragma unroll 8
    for (int k = 0; k < NH; k++) a = fmaf(Xs[k], W1T[k*65 + h], a);
    h1[h] = fmaxf(a, 0.f);
    __syncthreads();
    if (h < NA) {
        float o = hb2[h];
        #pragma unroll 8
        for (int k = 0; k < NH; k++) o = fmaf(h1[k], hw2[h*NH + k], o);
        out[row*NA + h] = o;
    }
}

// ---------------- launch ----------------
extern "C" void kernel_launch(void* const* d_in, const int* in_sizes, int n_in,
                              void* d_out, int out_size) {
    const float* X   = (const float*)d_in[0];
    const float* E   = (const float*)d_in[1];
    const float* W3  = (const float*)d_in[2];
    const float* W4  = (const float*)d_in[3];
    const float* W5  = (const float*)d_in[4];
    const float* W6  = (const float*)d_in[5];
    const float* ng  = (const float*)d_in[6];
    const float* nb  = (const float*)d_in[7];
    const float* eg  = (const float*)d_in[8];
    const float* eb  = (const float*)d_in[9];
    const float* hw1 = (const float*)d_in[10];
    const float* hb1 = (const float*)d_in[11];
    const float* hw2 = (const float*)d_in[12];
    const float* hb2 = (const float*)d_in[13];
    float* out = (float*)d_out;

    cudaFuncSetAttribute(k_main, cudaFuncAttributeMaxDynamicSharedMemorySize,
                         SMEM_MAIN_BYTES);

    k_sums<<<1, 128>>>(W3, W4);
    for (int l = 0; l < NL; l++) {
        k_xpre<<<NB*NN, NH>>>(X, W5, W6, l);
        k_main<<<NB*NN, NN, SMEM_MAIN_BYTES>>>(E, W4, eg, eb, l);
        k_xpost<<<NB*NN, NH>>>(X, ng, nb, l);
    }
    k_head<<<NB*NN, NH>>>(hw1, hb1, hw2, hb2, out);
}

// round 5
// speedup vs baseline: 2.1926x; 1.5129x over previous
#include <cuda_runtime.h>
#include <cuda_fp16.h>
#include <cstdint>
#include <cstddef>

#define NB 8
#define NN 256
#define NH 64
#define NL 2
#define NA 10
#define LN_EPS 1e-5f

// fp16 SMEM strides: 72 halfs/row (36 words) -> conflict-free frag loads (4*gid+tig)
#define HST 72

// SMEM byte offsets for k_main
#define OB_ES   0                       // half [256][72] = 36864B
#define OB_W4   36864                   // half [64][72]  = 9216B
#define OB_LG   46080                   // float[256]
#define OB_SALL 47104                   // float[256]
#define OB_ATT  48128                   // float[256]
#define OB_WAGG 49152                   // float[8][64]
#define OB_RED  51200                   // float[16]
#define OB_EG   51264                   // float[64]
#define OB_EB   51520                   // float[64]
#define SMEM_MAIN_BYTES 51776

// ---------------- device scratch ----------------
__device__ float g_E1[(size_t)NB*NN*NN*NH];   // 128 MB inter-layer E buffer
__device__ float g_Xbuf[NB*NN*NH];
__device__ float g_XJ[NB*NN*NH];              // X @ W5^T
__device__ float g_XR[NB*NN*NH];              // X @ W6^T
__device__ float g_AGG[NB*NN*NH];             // einsum result
__device__ float g_S[NB*NN];                  // row sums of Xi
__device__ float g_w3s[NL*NH];
__device__ float g_w4s[NL*NH];

// ---------------- fp16 mma.sync m16n8k16 ----------------
__device__ __forceinline__ void mma_f16(float* c, const uint32_t* a,
                                        uint32_t b0, uint32_t b1) {
    asm volatile(
        "mma.sync.aligned.m16n8k16.row.col.f32.f16.f16.f32 "
        "{%0,%1,%2,%3}, {%4,%5,%6,%7}, {%8,%9}, {%0,%1,%2,%3};"
        : "+f"(c[0]), "+f"(c[1]), "+f"(c[2]), "+f"(c[3])
        : "r"(a[0]), "r"(a[1]), "r"(a[2]), "r"(a[3]), "r"(b0), "r"(b1));
}

// ---------------- tiny precompute: column sums of W3 / W4 ----------------
__global__ void k_sums(const float* __restrict__ W3, const float* __restrict__ W4) {
    int t = threadIdx.x;            // 128 threads: (layer, k)
    int l = t >> 6, k = t & 63;
    float s3 = 0.f, s4 = 0.f;
    #pragma unroll 8
    for (int h = 0; h < NH; h++) {
        s3 += W3[(l*NH + h)*NH + k];
        s4 += W4[(l*NH + h)*NH + k];
    }
    g_w3s[t] = s3;
    g_w4s[t] = s4;
}

// ---------------- per-row X-path pre: s, Xj=X@W5^T, Xres=X@W6^T ----------------
__global__ void k_xpre(const float* __restrict__ X0, const float* __restrict__ W5,
                       const float* __restrict__ W6, int layer) {
    __shared__ float Xs[NH];
    __shared__ float W5T[NH*65];
    __shared__ float W6T[NH*65];
    __shared__ float red[2];
    const float* Xin  = layer ? g_Xbuf : X0;
    const float* W5l  = W5 + layer*NH*NH;
    const float* W6l  = W6 + layer*NH*NH;
    const float* w3sl = g_w3s + layer*NH;

    int row = blockIdx.x, h = threadIdx.x;
    Xs[h] = Xin[row*NH + h];
    for (int idx = h; idx < NH*NH; idx += NH) {
        int r = idx >> 6, k = idx & 63;
        W5T[k*65 + r] = W5l[idx];
        W6T[k*65 + r] = W6l[idx];
    }
    __syncthreads();

    float a5 = 0.f, a6 = 0.f;
    #pragma unroll 8
    for (int k = 0; k < NH; k++) {
        float x = Xs[k];
        a5 = fmaf(x, W5T[k*65 + h], a5);
        a6 = fmaf(x, W6T[k*65 + h], a6);
    }
    g_XJ[row*NH + h] = a5;
    g_XR[row*NH + h] = a6;

    float p = Xs[h] * w3sl[h];
    #pragma unroll
    for (int o = 16; o; o >>= 1) p += __shfl_xor_sync(0xffffffffu, p, o);
    if ((h & 31) == 0) red[h >> 5] = p;
    __syncthreads();
    if (h == 0) g_S[row] = red[0] + red[1];
}

// ---------------- main fused kernel (fp16 tensor GEMM, fragment epilogue) ----------------
__global__ void __launch_bounds__(256, 2) k_main(
    const float* __restrict__ E0, const float* __restrict__ W4,
    const float* __restrict__ eg, const float* __restrict__ eb, int layer) {
    extern __shared__ char smc[];
    __half* Es16 = reinterpret_cast<__half*>(smc + OB_ES);
    __half* Wh   = reinterpret_cast<__half*>(smc + OB_W4);
    float* lgA  = reinterpret_cast<float*>(smc + OB_LG);
    float* sA   = reinterpret_cast<float*>(smc + OB_SALL);
    float* attA = reinterpret_cast<float*>(smc + OB_ATT);
    float* wagg = reinterpret_cast<float*>(smc + OB_WAGG);
    float* red  = reinterpret_cast<float*>(smc + OB_RED);
    float* egs  = reinterpret_cast<float*>(smc + OB_EG);
    float* ebs  = reinterpret_cast<float*>(smc + OB_EB);

    const float* Ein = layer ? g_E1 : E0;
    const float* W4l = W4 + layer*NH*NH;

    const int bi = blockIdx.x;
    const int b  = bi >> 8;
    const int t  = threadIdx.x;
    const int w  = t >> 5;
    const int lane = t & 31;
    const int gid = lane >> 2, tig = lane & 3;

    // --- E load (fp32, coalesced float4) + exact logit partials + fp16 SMEM store ---
    {
        const float4* Eg4 = reinterpret_cast<const float4*>(Ein + (size_t)bi*NN*NH);
        const int q = t >> 4, k4 = t & 15;
        const float4 wv = *reinterpret_cast<const float4*>(g_w4s + layer*NH + 4*k4);
        float part[16];
        #pragma unroll
        for (int c = 0; c < 16; c++) {
            int idx4 = t + 256*c;
            float4 v = Eg4[idx4];
            int j = idx4 >> 4;
            part[c] = v.x*wv.x + v.y*wv.y + v.z*wv.z + v.w*wv.w;
            __half2* dst = reinterpret_cast<__half2*>(Es16 + j*HST + 4*k4);
            dst[0] = __floats2half2_rn(v.x, v.y);
            dst[1] = __floats2half2_rn(v.z, v.w);
        }
        // reduce 16 per-row partials over the 16-lane group
        #pragma unroll
        for (int o = 1; o <= 8; o <<= 1)
            #pragma unroll
            for (int c = 0; c < 16; c++)
                part[c] += __shfl_xor_sync(0xffffffffu, part[c], o);
        lgA[q + 16*k4] = part[k4];
    }
    // --- W4 layer slice -> fp16 SMEM (row-major [h][k]) ---
    {
        const float2* Wg2 = reinterpret_cast<const float2*>(W4l);
        #pragma unroll
        for (int c = 0; c < 8; c++) {
            int idx2 = t + 256*c;
            int h = idx2 >> 5, k2 = idx2 & 31;
            float2 vw = Wg2[idx2];
            *reinterpret_cast<__half2*>(Wh + h*HST + 2*k2) = __floats2half2_rn(vw.x, vw.y);
        }
    }
    if (t < NH) {
        egs[t] = eg[layer*NH + t];
        ebs[t] = eb[layer*NH + t];
    }
    sA[t] = g_S[b*NN + t];
    __syncthreads();

    // --- block softmax over 256 (thread t = row t) ---
    float lg = lgA[t] + g_S[bi] + sA[t];
    float m = lg;
    #pragma unroll
    for (int o = 16; o; o >>= 1) m = fmaxf(m, __shfl_xor_sync(0xffffffffu, m, o));
    if (lane == 0) red[w] = m;
    __syncthreads();
    if (t == 0) {
        float mm = red[0];
        for (int q = 1; q < 8; q++) mm = fmaxf(mm, red[q]);
        red[8] = mm;
    }
    __syncthreads();
    m = red[8];
    float ex = expf(lg - m);
    float sum = ex;
    #pragma unroll
    for (int o = 16; o; o >>= 1) sum += __shfl_xor_sync(0xffffffffu, sum, o);
    if (lane == 0) red[w] = sum;
    __syncthreads();
    if (t == 0) {
        float s8 = 0.f;
        for (int q = 0; q < 8; q++) s8 += red[q];
        red[9] = 1.f / s8;
    }
    __syncthreads();
    attA[t] = ex * red[9];
    __syncthreads();

    // --- fp16 tensor GEMM: warp w -> rows [w*32, w*32+32), cols 0..63 ---
    float acc[2][8][4];
    #pragma unroll
    for (int mt = 0; mt < 2; mt++)
        #pragma unroll
        for (int nt = 0; nt < 8; nt++)
            #pragma unroll
            for (int q = 0; q < 4; q++) acc[mt][nt][q] = 0.f;

    const uint32_t* EsU = reinterpret_cast<const uint32_t*>(Es16);
    const uint32_t* WU  = reinterpret_cast<const uint32_t*>(Wh);
    #pragma unroll
    for (int ks = 0; ks < 4; ks++) {
        const int kw = 8*ks + tig;        // word offset within row
        uint32_t a[2][4];
        #pragma unroll
        for (int mt = 0; mt < 2; mt++) {
            const int r0 = w*32 + mt*16 + gid;
            a[mt][0] = EsU[r0*36 + kw];
            a[mt][1] = EsU[(r0 + 8)*36 + kw];
            a[mt][2] = EsU[r0*36 + kw + 4];
            a[mt][3] = EsU[(r0 + 8)*36 + kw + 4];
        }
        #pragma unroll
        for (int nt = 0; nt < 8; nt++) {
            const int n = nt*8 + gid;
            uint32_t b0 = WU[n*36 + kw];
            uint32_t b1 = WU[n*36 + kw + 4];
            mma_f16(acc[0][nt], a[0], b0, b1);
            mma_f16(acc[1][nt], a[1], b0, b1);
        }
    }

    // --- fragment epilogue: att scale, LN stats, fragment agg, (layer0) LN+E1 STG ---
    float aggp[16];
    #pragma unroll
    for (int z = 0; z < 16; z++) aggp[z] = 0.f;
    const float* XJb = g_XJ + (size_t)b*NN*NH;
    float* E1o = g_E1 + (size_t)bi*NN*NH;

    #pragma unroll
    for (int mt = 0; mt < 2; mt++) {
        const int rA = w*32 + mt*16 + gid;
        const int rB = rA + 8;
        const float aA = attA[rA], aB = attA[rB];
        float s0 = 0.f, q0 = 0.f, s1 = 0.f, q1 = 0.f;
        #pragma unroll
        for (int nt = 0; nt < 8; nt++) {
            float e0 = acc[mt][nt][0] * aA;
            float e1 = acc[mt][nt][1] * aA;
            float e2 = acc[mt][nt][2] * aB;
            float e3 = acc[mt][nt][3] * aB;
            acc[mt][nt][0] = e0; acc[mt][nt][1] = e1;
            acc[mt][nt][2] = e2; acc[mt][nt][3] = e3;
            s0 += e0 + e1; q0 += e0*e0 + e1*e1;
            s1 += e2 + e3; q1 += e2*e2 + e3*e3;
            const int hc = nt*8 + 2*tig;
            float2 xA = *reinterpret_cast<const float2*>(XJb + rA*NH + hc);
            float2 xB = *reinterpret_cast<const float2*>(XJb + rB*NH + hc);
            aggp[2*nt]     += e0*xA.x + e2*xB.x;
            aggp[2*nt + 1] += e1*xA.y + e3*xB.y;
        }
        // row LN stats: reduce over tig group (4 lanes cover all 64 cols)
        #pragma unroll
        for (int o = 1; o <= 2; o <<= 1) {
            s0 += __shfl_xor_sync(0xffffffffu, s0, o);
            q0 += __shfl_xor_sync(0xffffffffu, q0, o);
            s1 += __shfl_xor_sync(0xffffffffu, s1, o);
            q1 += __shfl_xor_sync(0xffffffffu, q1, o);
        }
        if (layer == 0) {
            const float mA = s0 * (1.f/NH);
            const float rsA = rsqrtf(fmaf(q0, 1.f/NH, -mA*mA) + LN_EPS);
            const float mB = s1 * (1.f/NH);
            const float rsB = rsqrtf(fmaf(q1, 1.f/NH, -mB*mB) + LN_EPS);
            #pragma unroll
            for (int nt = 0; nt < 8; nt++) {
                const int hc = nt*8 + 2*tig;
                const float2 g2 = *reinterpret_cast<const float2*>(egs + hc);
                const float2 b2 = *reinterpret_cast<const float2*>(ebs + hc);
                float2 vA = {(acc[mt][nt][0] - mA)*rsA*g2.x + b2.x,
                             (acc[mt][nt][1] - mA)*rsA*g2.y + b2.y};
                float2 vB = {(acc[mt][nt][2] - mB)*rsB*g2.x + b2.x,
                             (acc[mt][nt][3] - mB)*rsB*g2.y + b2.y};
                *reinterpret_cast<float2*>(E1o + rA*NH + hc) = vA;
                *reinterpret_cast<float2*>(E1o + rB*NH + hc) = vB;
            }
        }
    }

    // --- agg: reduce fragment partials over gid lanes, then across warps ---
    #pragma unroll
    for (int o = 4; o <= 16; o <<= 1)
        #pragma unroll
        for (int z = 0; z < 16; z++)
            aggp[z] += __shfl_xor_sync(0xffffffffu, aggp[z], o);
    if (gid == 0) {
        #pragma unroll
        for (int nt = 0; nt < 8; nt++) {
            wagg[w*64 + nt*8 + 2*tig]     = aggp[2*nt];
            wagg[w*64 + nt*8 + 2*tig + 1] = aggp[2*nt + 1];
        }
    }
    __syncthreads();
    if (t < NH) {
        float s = 0.f;
        #pragma unroll
        for (int q = 0; q < 8; q++) s += wagg[q*64 + t];
        g_AGG[bi*NH + t] = s;
    }
}

// ---------------- X update: X = LN(relu(agg + Xres)) + X ----------------
__global__ void k_xpost(const float* __restrict__ X0, const float* __restrict__ ng,
                        const float* __restrict__ nb, int layer) {
    __shared__ float red[2];
    __shared__ float bc[2];
    const float* Xin = layer ? g_Xbuf : X0;
    int row = blockIdx.x, h = threadIdx.x;

    float v = g_AGG[row*NH + h] + g_XR[row*NH + h];
    v = fmaxf(v, 0.f);

    float p = v;
    #pragma unroll
    for (int o = 16; o; o >>= 1) p += __shfl_xor_sync(0xffffffffu, p, o);
    if ((h & 31) == 0) red[h >> 5] = p;
    __syncthreads();
    if (h == 0) bc[0] = (red[0] + red[1]) * (1.f/NH);
    __syncthreads();
    float mean = bc[0];
    float d = v - mean;
    p = d*d;
    #pragma unroll
    for (int o = 16; o; o >>= 1) p += __shfl_xor_sync(0xffffffffu, p, o);
    if ((h & 31) == 0) red[h >> 5] = p;
    __syncthreads();
    if (h == 0) bc[1] = rsqrtf((red[0] + red[1]) * (1.f/NH) + LN_EPS);
    __syncthreads();

    float out = d * bc[1] * ng[layer*NH + h] + nb[layer*NH + h] + Xin[row*NH + h];
    g_Xbuf[row*NH + h] = out;
}

// ---------------- head: out = relu(X@hw1^T + hb1) @ hw2^T + hb2 ----------------
__global__ void k_head(const float* __restrict__ hw1, const float* __restrict__ hb1,
                       const float* __restrict__ hw2, const float* __restrict__ hb2,
                       float* __restrict__ out) {
    __shared__ float Xs[NH];
    __shared__ float W1T[NH*65];
    __shared__ float h1[NH];
    int row = blockIdx.x, h = threadIdx.x;
    Xs[h] = g_Xbuf[row*NH + h];
    for (int idx = h; idx < NH*NH; idx += NH) {
        int r = idx >> 6, k = idx & 63;
        W1T[k*65 + r] = hw1[idx];
    }
    __syncthreads();
    float a = hb1[h];
    #pragma unroll 8
    for (int k = 0; k < NH; k++) a = fmaf(Xs[k], W1T[k*65 + h], a);
    h1[h] = fmaxf(a, 0.f);
    __syncthreads();
    if (h < NA) {
        float o = hb2[h];
        #pragma unroll 8
        for (int k = 0; k < NH; k++) o = fmaf(h1[k], hw2[h*NH + k], o);
        out[row*NA + h] = o;
    }
}

// ---------------- launch ----------------
extern "C" void kernel_launch(void* const* d_in, const int* in_sizes, int n_in,
                              void* d_out, int out_size) {
    const float* X   = (const float*)d_in[0];
    const float* E   = (const float*)d_in[1];
    const float* W3  = (const float*)d_in[2];
    const float* W4  = (const float*)d_in[3];
    const float* W5  = (const float*)d_in[4];
    const float* W6  = (const float*)d_in[5];
    const float* ng  = (const float*)d_in[6];
    const float* nb  = (const float*)d_in[7];
    const float* eg  = (const float*)d_in[8];
    const float* eb  = (const float*)d_in[9];
    const float* hw1 = (const float*)d_in[10];
    const float* hb1 = (const float*)d_in[11];
    const float* hw2 = (const float*)d_in[12];
    const float* hb2 = (const float*)d_in[13];
    float* out = (float*)d_out;

    cudaFuncSetAttribute(k_main, cudaFuncAttributeMaxDynamicSharedMemorySize,
                         SMEM_MAIN_BYTES);

    k_sums<<<1, 128>>>(W3, W4);
    for (int l = 0; l < NL; l++) {
        k_xpre<<<NB*NN, NH>>>(X, W5, W6, l);
        k_main<<<NB*NN, NN, SMEM_MAIN_BYTES>>>(E, W4, eg, eb, l);
        k_xpost<<<NB*NN, NH>>>(X, ng, nb, l);
    }
    k_head<<<NB*NN, NH>>>(hw1, hb1, hw2, hb2, out);
}

// round 6
// speedup vs baseline: 2.6109x; 1.1908x over previous
#include <cuda_runtime.h>
#include <cuda_fp16.h>
#include <cstdint>
#include <cstddef>

#define NB 8
#define NN 256
#define NH 64
#define NL 2
#define NA 10
#define LN_EPS 1e-5f

// fp16 SMEM stride: 72 halfs/row (36 words) -> conflict-free frag loads (4*gid+tig)
#define HST 72

// SMEM byte offsets for k_main
#define OB_ES   0                       // half [256][72] = 36864B
#define OB_W4   36864                   // half [64][72]  = 9216B
#define OB_LG   46080                   // float[256]
#define OB_SALL 47104                   // float[256]
#define OB_ATT  48128                   // float[256]
#define OB_WAGG 49152                   // float[8][64]
#define OB_RED  51200                   // float[16]
#define OB_EG   51264                   // float[64]
#define OB_EB   51520                   // float[64]
#define OB_W4S1 51776                   // float[64] (w4sum of layer 1)
#define SMEM_MAIN_BYTES 52032

// ---------------- device scratch ----------------
__device__ __half g_E1h[(size_t)NB*NN*NN*NH]; // 64 MB inter-layer E buffer (fp16, LN'd)
__device__ float  g_LG1[NB*NN*NN];            // 2 MB: layer-1 logit partials (fp32 exact)
__device__ float  g_Xbuf[NB*NN*NH];
__device__ __half g_XJh[NB*NN*NH];            // X @ W5^T (fp16)
__device__ float  g_XR[NB*NN*NH];             // X @ W6^T
__device__ float  g_AGG[NB*NN*NH];            // einsum result
__device__ float  g_S[NB*NN];                 // row sums of Xi
__device__ float  g_w3s[NL*NH];
__device__ float  g_w4s[NL*NH];

// ---------------- fp16 mma.sync m16n8k16 ----------------
__device__ __forceinline__ void mma_f16(float* c, const uint32_t* a,
                                        uint32_t b0, uint32_t b1) {
    asm volatile(
        "mma.sync.aligned.m16n8k16.row.col.f32.f16.f16.f32 "
        "{%0,%1,%2,%3}, {%4,%5,%6,%7}, {%8,%9}, {%0,%1,%2,%3};"
        : "+f"(c[0]), "+f"(c[1]), "+f"(c[2]), "+f"(c[3])
        : "r"(a[0]), "r"(a[1]), "r"(a[2]), "r"(a[3]), "r"(b0), "r"(b1));
}

// ---------------- column sums of W3 / W4 ----------------
__global__ void k_sums(const float* __restrict__ W3, const float* __restrict__ W4) {
    int t = threadIdx.x;            // 128 threads: (layer, k)
    int l = t >> 6, k = t & 63;
    float s3 = 0.f, s4 = 0.f;
    #pragma unroll 8
    for (int h = 0; h < NH; h++) {
        s3 += W3[(l*NH + h)*NH + k];
        s4 += W4[(l*NH + h)*NH + k];
    }
    g_w3s[t] = s3;
    g_w4s[t] = s4;
}

// ---------------- layer-0 X pre: s0, XJ0, XR0 (4 rows per 256-thread block) ----------
__global__ void k_xstart(const float* __restrict__ X0, const float* __restrict__ W5,
                         const float* __restrict__ W6) {
    __shared__ float W5T[NH*65];
    __shared__ float W6T[NH*65];
    __shared__ float Xs[4*NH];
    __shared__ float red[8];
    const int t = threadIdx.x, ri = t >> 6, h = t & 63;
    const int row = blockIdx.x*4 + ri;

    for (int idx = t; idx < NH*NH; idx += 256) {
        int r = idx >> 6, k = idx & 63;
        W5T[k*65 + r] = W5[idx];
        W6T[k*65 + r] = W6[idx];
    }
    Xs[t] = X0[row*NH + h];
    __syncthreads();

    float a5 = 0.f, a6 = 0.f;
    #pragma unroll 8
    for (int k = 0; k < NH; k++) {
        float x = Xs[ri*NH + k];
        a5 = fmaf(x, W5T[k*65 + h], a5);
        a6 = fmaf(x, W6T[k*65 + h], a6);
    }
    g_XJh[row*NH + h] = __float2half(a5);
    g_XR[row*NH + h]  = a6;

    float p = Xs[t] * g_w3s[h];
    #pragma unroll
    for (int o = 16; o; o >>= 1) p += __shfl_xor_sync(0xffffffffu, p, o);
    if ((t & 31) == 0) red[t >> 5] = p;
    __syncthreads();
    if (h == 0) g_S[row] = red[2*ri] + red[2*ri + 1];
}

// ---------------- mid: X1 = LN(relu(agg+XR0))+X0, then s1, XJ1, XR1 ----------------
__global__ void k_xmid(const float* __restrict__ X0, const float* __restrict__ W5,
                       const float* __restrict__ W6, const float* __restrict__ ng,
                       const float* __restrict__ nb) {
    __shared__ float W5T[NH*65];
    __shared__ float W6T[NH*65];
    __shared__ float Xs[4*NH];
    __shared__ float red[8];
    __shared__ float red2[8];
    const int t = threadIdx.x, ri = t >> 6, h = t & 63;
    const int row = blockIdx.x*4 + ri;

    for (int idx = t; idx < NH*NH; idx += 256) {
        int r = idx >> 6, k = idx & 63;
        W5T[k*65 + r] = W5[NH*NH + idx];
        W6T[k*65 + r] = W6[NH*NH + idx];
    }

    float v = fmaxf(g_AGG[row*NH + h] + g_XR[row*NH + h], 0.f);
    float p = v;
    #pragma unroll
    for (int o = 16; o; o >>= 1) p += __shfl_xor_sync(0xffffffffu, p, o);
    if ((t & 31) == 0) red[t >> 5] = p;
    __syncthreads();
    float mean = (red[2*ri] + red[2*ri + 1]) * (1.f/NH);
    float d = v - mean;
    p = d*d;
    #pragma unroll
    for (int o = 16; o; o >>= 1) p += __shfl_xor_sync(0xffffffffu, p, o);
    if ((t & 31) == 0) red2[t >> 5] = p;
    __syncthreads();
    float rstd = rsqrtf((red2[2*ri] + red2[2*ri + 1]) * (1.f/NH) + LN_EPS);
    float x1 = d*rstd*ng[h] + nb[h] + X0[row*NH + h];
    g_Xbuf[row*NH + h] = x1;
    Xs[t] = x1;
    __syncthreads();

    float a5 = 0.f, a6 = 0.f;
    #pragma unroll 8
    for (int k = 0; k < NH; k++) {
        float x = Xs[ri*NH + k];
        a5 = fmaf(x, W5T[k*65 + h], a5);
        a6 = fmaf(x, W6T[k*65 + h], a6);
    }
    g_XJh[row*NH + h] = __float2half(a5);
    g_XR[row*NH + h]  = a6;

    p = x1 * g_w3s[NH + h];
    #pragma unroll
    for (int o = 16; o; o >>= 1) p += __shfl_xor_sync(0xffffffffu, p, o);
    if ((t & 31) == 0) red[t >> 5] = p;
    __syncthreads();
    if (h == 0) g_S[row] = red[2*ri] + red[2*ri + 1];
}

// ---------------- final: X2 = LN(relu(agg+XR1))+X1, then head -> out ----------------
__global__ void k_final(const float* __restrict__ ng, const float* __restrict__ nb,
                        const float* __restrict__ hw1, const float* __restrict__ hb1,
                        const float* __restrict__ hw2, const float* __restrict__ hb2,
                        float* __restrict__ out) {
    __shared__ float W1T[NH*65];
    __shared__ float Xs[4*NH];
    __shared__ float h1s[4*NH];
    __shared__ float red[8];
    __shared__ float red2[8];
    const int t = threadIdx.x, ri = t >> 6, h = t & 63;
    const int row = blockIdx.x*4 + ri;

    for (int idx = t; idx < NH*NH; idx += 256) {
        int r = idx >> 6, k = idx & 63;
        W1T[k*65 + r] = hw1[idx];
    }

    float v = fmaxf(g_AGG[row*NH + h] + g_XR[row*NH + h], 0.f);
    float p = v;
    #pragma unroll
    for (int o = 16; o; o >>= 1) p += __shfl_xor_sync(0xffffffffu, p, o);
    if ((t & 31) == 0) red[t >> 5] = p;
    __syncthreads();
    float mean = (red[2*ri] + red[2*ri + 1]) * (1.f/NH);
    float d = v - mean;
    p = d*d;
    #pragma unroll
    for (int o = 16; o; o >>= 1) p += __shfl_xor_sync(0xffffffffu, p, o);
    if ((t & 31) == 0) red2[t >> 5] = p;
    __syncthreads();
    float rstd = rsqrtf((red2[2*ri] + red2[2*ri + 1]) * (1.f/NH) + LN_EPS);
    Xs[t] = d*rstd*ng[NH + h] + nb[NH + h] + g_Xbuf[row*NH + h];
    __syncthreads();

    float a = hb1[h];
    #pragma unroll 8
    for (int k = 0; k < NH; k++) a = fmaf(Xs[ri*NH + k], W1T[k*65 + h], a);
    h1s[t] = fmaxf(a, 0.f);
    __syncthreads();

    if (h < NA) {
        float o = hb2[h];
        #pragma unroll 8
        for (int k = 0; k < NH; k++) o = fmaf(h1s[ri*NH + k], hw2[h*NH + k], o);
        out[row*NA + h] = o;
    }
}

// ---------------- main fused kernel ----------------
__global__ void __launch_bounds__(256, 2) k_main(
    const float* __restrict__ E0, const float* __restrict__ W4,
    const float* __restrict__ eg, const float* __restrict__ eb, int layer) {
    extern __shared__ char smc[];
    __half* Es16 = reinterpret_cast<__half*>(smc + OB_ES);
    __half* Wh   = reinterpret_cast<__half*>(smc + OB_W4);
    float* lgA  = reinterpret_cast<float*>(smc + OB_LG);
    float* sA   = reinterpret_cast<float*>(smc + OB_SALL);
    float* attA = reinterpret_cast<float*>(smc + OB_ATT);
    float* wagg = reinterpret_cast<float*>(smc + OB_WAGG);
    float* red  = reinterpret_cast<float*>(smc + OB_RED);
    float* egs  = reinterpret_cast<float*>(smc + OB_EG);
    float* ebs  = reinterpret_cast<float*>(smc + OB_EB);
    float* w41s = reinterpret_cast<float*>(smc + OB_W4S1);

    const float* W4l = W4 + layer*NH*NH;

    const int bi = blockIdx.x;
    const int b  = bi >> 8;
    const int t  = threadIdx.x;
    const int w  = t >> 5;
    const int lane = t & 31;
    const int gid = lane >> 2, tig = lane & 3;

    if (layer == 0) {
        // E load (fp32) + exact logit partials + fp16 SMEM store
        const float4* Eg4 = reinterpret_cast<const float4*>(E0 + (size_t)bi*NN*NH);
        const int q = t >> 4, k4 = t & 15;
        const float4 wv = *reinterpret_cast<const float4*>(g_w4s + 4*k4);
        float part[16];
        #pragma unroll
        for (int c = 0; c < 16; c++) {
            int idx4 = t + 256*c;
            float4 v = Eg4[idx4];
            int j = idx4 >> 4;
            part[c] = v.x*wv.x + v.y*wv.y + v.z*wv.z + v.w*wv.w;
            __half2* dst = reinterpret_cast<__half2*>(Es16 + j*HST + 4*k4);
            dst[0] = __floats2half2_rn(v.x, v.y);
            dst[1] = __floats2half2_rn(v.z, v.w);
        }
        #pragma unroll
        for (int o = 1; o <= 8; o <<= 1)
            #pragma unroll
            for (int c = 0; c < 16; c++)
                part[c] += __shfl_xor_sync(0xffffffffu, part[c], o);
        lgA[q + 16*k4] = part[k4];
        if (t < NH) {
            egs[t]  = eg[t];
            ebs[t]  = eb[t];
            w41s[t] = g_w4s[NH + t];
        }
    } else {
        // E1 load (fp16 direct, 32KB)
        const uint2* Eg2 = reinterpret_cast<const uint2*>(g_E1h + (size_t)bi*NN*NH);
        #pragma unroll
        for (int c = 0; c < 16; c++) {
            int idx2 = t + 256*c;
            int j = idx2 >> 4, qq = idx2 & 15;
            *reinterpret_cast<uint2*>(Es16 + j*HST + 4*qq) = Eg2[idx2];
        }
    }
    // W4 layer slice -> fp16 SMEM (row-major [h][k])
    {
        const float2* Wg2 = reinterpret_cast<const float2*>(W4l);
        #pragma unroll
        for (int c = 0; c < 8; c++) {
            int idx2 = t + 256*c;
            int h = idx2 >> 5, k2 = idx2 & 31;
            float2 vw = Wg2[idx2];
            *reinterpret_cast<__half2*>(Wh + h*HST + 2*k2) = __floats2half2_rn(vw.x, vw.y);
        }
    }
    sA[t] = g_S[b*NN + t];
    __syncthreads();

    // --- block softmax over 256 (thread t = row t) ---
    float lg = (layer ? g_LG1[(size_t)bi*NN + t] : lgA[t]) + g_S[bi] + sA[t];
    float m = lg;
    #pragma unroll
    for (int o = 16; o; o >>= 1) m = fmaxf(m, __shfl_xor_sync(0xffffffffu, m, o));
    if (lane == 0) red[w] = m;
    __syncthreads();
    if (t == 0) {
        float mm = red[0];
        for (int q = 1; q < 8; q++) mm = fmaxf(mm, red[q]);
        red[8] = mm;
    }
    __syncthreads();
    m = red[8];
    float ex = expf(lg - m);
    float sum = ex;
    #pragma unroll
    for (int o = 16; o; o >>= 1) sum += __shfl_xor_sync(0xffffffffu, sum, o);
    if (lane == 0) red[w] = sum;
    __syncthreads();
    if (t == 0) {
        float s8 = 0.f;
        for (int q = 0; q < 8; q++) s8 += red[q];
        red[9] = 1.f / s8;
    }
    __syncthreads();
    attA[t] = ex * red[9];
    __syncthreads();

    // --- fp16 tensor GEMM: warp w -> rows [w*32, w*32+32), cols 0..63 ---
    float acc[2][8][4];
    #pragma unroll
    for (int mt = 0; mt < 2; mt++)
        #pragma unroll
        for (int nt = 0; nt < 8; nt++)
            #pragma unroll
            for (int q = 0; q < 4; q++) acc[mt][nt][q] = 0.f;

    const uint32_t* EsU = reinterpret_cast<const uint32_t*>(Es16);
    const uint32_t* WU  = reinterpret_cast<const uint32_t*>(Wh);
    #pragma unroll
    for (int ks = 0; ks < 4; ks++) {
        const int kw = 8*ks + tig;
        uint32_t a[2][4];
        #pragma unroll
        for (int mt = 0; mt < 2; mt++) {
            const int r0 = w*32 + mt*16 + gid;
            a[mt][0] = EsU[r0*36 + kw];
            a[mt][1] = EsU[(r0 + 8)*36 + kw];
            a[mt][2] = EsU[r0*36 + kw + 4];
            a[mt][3] = EsU[(r0 + 8)*36 + kw + 4];
        }
        #pragma unroll
        for (int nt = 0; nt < 8; nt++) {
            const int n = nt*8 + gid;
            uint32_t b0 = WU[n*36 + kw];
            uint32_t b1 = WU[n*36 + kw + 4];
            mma_f16(acc[0][nt], a[0], b0, b1);
            mma_f16(acc[1][nt], a[1], b0, b1);
        }
    }

    // --- fragment epilogue ---
    float aggp[16];
    #pragma unroll
    for (int z = 0; z < 16; z++) aggp[z] = 0.f;
    const __half* XJb = g_XJh + (size_t)b*NN*NH;
    __half* E1o = g_E1h + (size_t)bi*NN*NH;
    float* LG1o = g_LG1 + (size_t)bi*NN;

    #pragma unroll
    for (int mt = 0; mt < 2; mt++) {
        const int rA = w*32 + mt*16 + gid;
        const int rB = rA + 8;
        const float aA = attA[rA], aB = attA[rB];
        float s0 = 0.f, q0 = 0.f, s1 = 0.f, q1 = 0.f;
        #pragma unroll
        for (int nt = 0; nt < 8; nt++) {
            float e0 = acc[mt][nt][0] * aA;
            float e1 = acc[mt][nt][1] * aA;
            float e2 = acc[mt][nt][2] * aB;
            float e3 = acc[mt][nt][3] * aB;
            acc[mt][nt][0] = e0; acc[mt][nt][1] = e1;
            acc[mt][nt][2] = e2; acc[mt][nt][3] = e3;
            const int hc = nt*8 + 2*tig;
            float2 xA = __half22float2(*reinterpret_cast<const __half2*>(XJb + rA*NH + hc));
            float2 xB = __half22float2(*reinterpret_cast<const __half2*>(XJb + rB*NH + hc));
            aggp[2*nt]     += e0*xA.x + e2*xB.x;
            aggp[2*nt + 1] += e1*xA.y + e3*xB.y;
            if (layer == 0) {
                s0 += e0 + e1; q0 += e0*e0 + e1*e1;
                s1 += e2 + e3; q1 += e2*e2 + e3*e3;
            }
        }
        if (layer == 0) {
            // row LN stats over tig group
            #pragma unroll
            for (int o = 1; o <= 2; o <<= 1) {
                s0 += __shfl_xor_sync(0xffffffffu, s0, o);
                q0 += __shfl_xor_sync(0xffffffffu, q0, o);
                s1 += __shfl_xor_sync(0xffffffffu, s1, o);
                q1 += __shfl_xor_sync(0xffffffffu, q1, o);
            }
            const float mA = s0 * (1.f/NH);
            const float rsA = rsqrtf(fmaf(q0, 1.f/NH, -mA*mA) + LN_EPS);
            const float mB = s1 * (1.f/NH);
            const float rsB = rsqrtf(fmaf(q1, 1.f/NH, -mB*mB) + LN_EPS);
            float lpA = 0.f, lpB = 0.f;
            #pragma unroll
            for (int nt = 0; nt < 8; nt++) {
                const int hc = nt*8 + 2*tig;
                const float2 g2 = *reinterpret_cast<const float2*>(egs + hc);
                const float2 b2 = *reinterpret_cast<const float2*>(ebs + hc);
                float vA0 = (acc[mt][nt][0] - mA)*rsA*g2.x + b2.x;
                float vA1 = (acc[mt][nt][1] - mA)*rsA*g2.y + b2.y;
                float vB0 = (acc[mt][nt][2] - mB)*rsB*g2.x + b2.x;
                float vB1 = (acc[mt][nt][3] - mB)*rsB*g2.y + b2.y;
                *reinterpret_cast<__half2*>(E1o + rA*NH + hc) = __floats2half2_rn(vA0, vA1);
                *reinterpret_cast<__half2*>(E1o + rB*NH + hc) = __floats2half2_rn(vB0, vB1);
                const float2 w2 = *reinterpret_cast<const float2*>(w41s + hc);
                lpA += vA0*w2.x + vA1*w2.y;
                lpB += vB0*w2.x + vB1*w2.y;
            }
            #pragma unroll
            for (int o = 1; o <= 2; o <<= 1) {
                lpA += __shfl_xor_sync(0xffffffffu, lpA, o);
                lpB += __shfl_xor_sync(0xffffffffu, lpB, o);
            }
            if (tig == 0) {
                LG1o[rA] = lpA;
                LG1o[rB] = lpB;
            }
        }
    }

    // --- agg: reduce fragment partials over gid lanes, then across warps ---
    #pragma unroll
    for (int o = 4; o <= 16; o <<= 1)
        #pragma unroll
        for (int z = 0; z < 16; z++)
            aggp[z] += __shfl_xor_sync(0xffffffffu, aggp[z], o);
    if (gid == 0) {
        #pragma unroll
        for (int nt = 0; nt < 8; nt++) {
            wagg[w*64 + nt*8 + 2*tig]     = aggp[2*nt];
            wagg[w*64 + nt*8 + 2*tig + 1] = aggp[2*nt + 1];
        }
    }
    __syncthreads();
    if (t < NH) {
        float s = 0.f;
        #pragma unroll
        for (int q = 0; q < 8; q++) s += wagg[q*64 + t];
        g_AGG[bi*NH + t] = s;
    }
}

// ---------------- launch ----------------
extern "C" void kernel_launch(void* const* d_in, const int* in_sizes, int n_in,
                              void* d_out, int out_size) {
    const float* X   = (const float*)d_in[0];
    const float* E   = (const float*)d_in[1];
    const float* W3  = (const float*)d_in[2];
    const float* W4  = (const float*)d_in[3];
    const float* W5  = (const float*)d_in[4];
    const float* W6  = (const float*)d_in[5];
    const float* ng  = (const float*)d_in[6];
    const float* nb  = (const float*)d_in[7];
    const float* eg  = (const float*)d_in[8];
    const float* eb  = (const float*)d_in[9];
    const float* hw1 = (const float*)d_in[10];
    const float* hb1 = (const float*)d_in[11];
    const float* hw2 = (const float*)d_in[12];
    const float* hb2 = (const float*)d_in[13];
    float* out = (float*)d_out;

    cudaFuncSetAttribute(k_main, cudaFuncAttributeMaxDynamicSharedMemorySize,
                         SMEM_MAIN_BYTES);

    k_sums<<<1, 128>>>(W3, W4);
    k_xstart<<<NB*NN/4, 256>>>(X, W5, W6);
    k_main<<<NB*NN, 256, SMEM_MAIN_BYTES>>>(E, W4, eg, eb, 0);
    k_xmid<<<NB*NN/4, 256>>>(X, W5, W6, ng, nb);
    k_main<<<NB*NN, 256, SMEM_MAIN_BYTES>>>(E, W4, eg, eb, 1);
    k_final<<<NB*NN/4, 256>>>(ng, nb, hw1, hb1, hw2, hb2, out);
}

// round 7
// speedup vs baseline: 3.1365x; 1.2013x over previous
#include <cuda_runtime.h>
#include <cuda_fp16.h>
#include <cstdint>
#include <cstddef>

#define NB 8
#define NN 256
#define NH 64
#define NL 2
#define NA 10
#define LN_EPS 1e-5f

// fp16 SMEM stride: 72 halfs/row (36 words) -> conflict-free frag loads (4*gid+tig)
#define HST 72

// SMEM byte offsets for k_main
#define OB_ES   0                       // half [256][72] = 36864B (A operand, then E1 staging)
#define OB_W4   36864                   // half [64][72]  = 9216B
#define OB_XJ   46080                   // half [256][72] = 36864B (XJ staged)
#define OB_LG   82944                   // float[256]
#define OB_SALL 83968                   // float[256]
#define OB_ATT  84992                   // float[256]
#define OB_WAGG 86016                   // float[8][64]
#define OB_RED  88064                   // float[16]
#define OB_EG   88128                   // float[64]
#define OB_EB   88384                   // float[64]
#define OB_W4S1 88640                   // float[64]
#define SMEM_MAIN_BYTES 88896

// ---------------- device scratch ----------------
__device__ __half g_E1h[(size_t)NB*NN*NN*NH]; // 64 MB inter-layer E buffer (fp16, LN'd)
__device__ float  g_LG1[NB*NN*NN];            // 2 MB: layer-1 logit partials (fp32 exact)
__device__ float  g_Xbuf[NB*NN*NH];
__device__ __half g_XJh[NB*NN*NH];            // X @ W5^T (fp16)
__device__ float  g_XR[NB*NN*NH];             // X @ W6^T
__device__ float  g_AGG[NB*NN*NH];            // einsum result
__device__ float  g_S[NB*NN];                 // row sums of Xi
__device__ float  g_w3s[NL*NH];
__device__ float  g_w4s[NL*NH];

// ---------------- fp16 mma.sync m16n8k16 ----------------
__device__ __forceinline__ void mma_f16(float* c, const uint32_t* a,
                                        uint32_t b0, uint32_t b1) {
    asm volatile(
        "mma.sync.aligned.m16n8k16.row.col.f32.f16.f16.f32 "
        "{%0,%1,%2,%3}, {%4,%5,%6,%7}, {%8,%9}, {%0,%1,%2,%3};"
        : "+f"(c[0]), "+f"(c[1]), "+f"(c[2]), "+f"(c[3])
        : "r"(a[0]), "r"(a[1]), "r"(a[2]), "r"(a[3]), "r"(b0), "r"(b1));
}

// ---------------- column sums of W3 / W4 ----------------
__global__ void k_sums(const float* __restrict__ W3, const float* __restrict__ W4) {
    int t = threadIdx.x;            // 128 threads: (layer, k)
    int l = t >> 6, k = t & 63;
    float s3 = 0.f, s4 = 0.f;
    #pragma unroll 8
    for (int h = 0; h < NH; h++) {
        s3 += W3[(l*NH + h)*NH + k];
        s4 += W4[(l*NH + h)*NH + k];
    }
    g_w3s[t] = s3;
    g_w4s[t] = s4;
}

// ---------------- layer-0 X pre: s0, XJ0, XR0 (8 rows per 512-thread block) ----------
__global__ void __launch_bounds__(512) k_xstart(
    const float* __restrict__ X0, const float* __restrict__ W5,
    const float* __restrict__ W6) {
    __shared__ float W5T[NH*65];
    __shared__ float W6T[NH*65];
    __shared__ float Xs[8*NH];
    __shared__ float red[16];
    const int t = threadIdx.x, ri = t >> 6, h = t & 63;
    const int row = blockIdx.x*8 + ri;

    for (int idx = t; idx < NH*NH; idx += 512) {
        int r = idx >> 6, k = idx & 63;
        W5T[k*65 + r] = W5[idx];
        W6T[k*65 + r] = W6[idx];
    }
    Xs[t] = X0[row*NH + h];
    __syncthreads();

    float a5 = 0.f, a6 = 0.f;
    #pragma unroll 8
    for (int k = 0; k < NH; k++) {
        float x = Xs[ri*NH + k];
        a5 = fmaf(x, W5T[k*65 + h], a5);
        a6 = fmaf(x, W6T[k*65 + h], a6);
    }
    g_XJh[row*NH + h] = __float2half(a5);
    g_XR[row*NH + h]  = a6;

    float p = Xs[t] * g_w3s[h];
    #pragma unroll
    for (int o = 16; o; o >>= 1) p += __shfl_xor_sync(0xffffffffu, p, o);
    if ((t & 31) == 0) red[t >> 5] = p;
    __syncthreads();
    if (h == 0) g_S[row] = red[2*ri] + red[2*ri + 1];
}

// ---------------- mid: X1 = LN(relu(agg+XR0))+X0, then s1, XJ1, XR1 ----------------
__global__ void __launch_bounds__(512) k_xmid(
    const float* __restrict__ X0, const float* __restrict__ W5,
    const float* __restrict__ W6, const float* __restrict__ ng,
    const float* __restrict__ nb) {
    __shared__ float W5T[NH*65];
    __shared__ float W6T[NH*65];
    __shared__ float Xs[8*NH];
    __shared__ float red[16];
    __shared__ float red2[16];
    const int t = threadIdx.x, ri = t >> 6, h = t & 63;
    const int row = blockIdx.x*8 + ri;

    for (int idx = t; idx < NH*NH; idx += 512) {
        int r = idx >> 6, k = idx & 63;
        W5T[k*65 + r] = W5[NH*NH + idx];
        W6T[k*65 + r] = W6[NH*NH + idx];
    }

    float v = fmaxf(g_AGG[row*NH + h] + g_XR[row*NH + h], 0.f);
    float p = v;
    #pragma unroll
    for (int o = 16; o; o >>= 1) p += __shfl_xor_sync(0xffffffffu, p, o);
    if ((t & 31) == 0) red[t >> 5] = p;
    __syncthreads();
    float mean = (red[2*ri] + red[2*ri + 1]) * (1.f/NH);
    float d = v - mean;
    p = d*d;
    #pragma unroll
    for (int o = 16; o; o >>= 1) p += __shfl_xor_sync(0xffffffffu, p, o);
    if ((t & 31) == 0) red2[t >> 5] = p;
    __syncthreads();
    float rstd = rsqrtf((red2[2*ri] + red2[2*ri + 1]) * (1.f/NH) + LN_EPS);
    float x1 = d*rstd*ng[h] + nb[h] + X0[row*NH + h];
    g_Xbuf[row*NH + h] = x1;
    Xs[t] = x1;
    __syncthreads();

    float a5 = 0.f, a6 = 0.f;
    #pragma unroll 8
    for (int k = 0; k < NH; k++) {
        float x = Xs[ri*NH + k];
        a5 = fmaf(x, W5T[k*65 + h], a5);
        a6 = fmaf(x, W6T[k*65 + h], a6);
    }
    g_XJh[row*NH + h] = __float2half(a5);
    g_XR[row*NH + h]  = a6;

    p = x1 * g_w3s[NH + h];
    #pragma unroll
    for (int o = 16; o; o >>= 1) p += __shfl_xor_sync(0xffffffffu, p, o);
    if ((t & 31) == 0) red[t >> 5] = p;
    __syncthreads();
    if (h == 0) g_S[row] = red[2*ri] + red[2*ri + 1];
}

// ---------------- final: X2 = LN(relu(agg+XR1))+X1, then head -> out ----------------
__global__ void __launch_bounds__(512) k_final(
    const float* __restrict__ ng, const float* __restrict__ nb,
    const float* __restrict__ hw1, const float* __restrict__ hb1,
    const float* __restrict__ hw2, const float* __restrict__ hb2,
    float* __restrict__ out) {
    __shared__ float W1T[NH*65];
    __shared__ float Xs[8*NH];
    __shared__ float h1s[8*NH];
    __shared__ float red[16];
    __shared__ float red2[16];
    const int t = threadIdx.x, ri = t >> 6, h = t & 63;
    const int row = blockIdx.x*8 + ri;

    for (int idx = t; idx < NH*NH; idx += 512) {
        int r = idx >> 6, k = idx & 63;
        W1T[k*65 + r] = hw1[idx];
    }

    float v = fmaxf(g_AGG[row*NH + h] + g_XR[row*NH + h], 0.f);
    float p = v;
    #pragma unroll
    for (int o = 16; o; o >>= 1) p += __shfl_xor_sync(0xffffffffu, p, o);
    if ((t & 31) == 0) red[t >> 5] = p;
    __syncthreads();
    float mean = (red[2*ri] + red[2*ri + 1]) * (1.f/NH);
    float d = v - mean;
    p = d*d;
    #pragma unroll
    for (int o = 16; o; o >>= 1) p += __shfl_xor_sync(0xffffffffu, p, o);
    if ((t & 31) == 0) red2[t >> 5] = p;
    __syncthreads();
    float rstd = rsqrtf((red2[2*ri] + red2[2*ri + 1]) * (1.f/NH) + LN_EPS);
    Xs[t] = d*rstd*ng[NH + h] + nb[NH + h] + g_Xbuf[row*NH + h];
    __syncthreads();

    float a = hb1[h];
    #pragma unroll 8
    for (int k = 0; k < NH; k++) a = fmaf(Xs[ri*NH + k], W1T[k*65 + h], a);
    h1s[t] = fmaxf(a, 0.f);
    __syncthreads();

    if (h < NA) {
        float o = hb2[h];
        #pragma unroll 8
        for (int k = 0; k < NH; k++) o = fmaf(h1s[ri*NH + k], hw2[h*NH + k], o);
        out[row*NA + h] = o;
    }
}

// ---------------- main fused kernel ----------------
__global__ void __launch_bounds__(256, 2) k_main(
    const float* __restrict__ E0, const float* __restrict__ W4,
    const float* __restrict__ eg, const float* __restrict__ eb, int layer) {
    extern __shared__ char smc[];
    __half* Es16 = reinterpret_cast<__half*>(smc + OB_ES);
    __half* Wh   = reinterpret_cast<__half*>(smc + OB_W4);
    __half* XJs  = reinterpret_cast<__half*>(smc + OB_XJ);
    float* lgA  = reinterpret_cast<float*>(smc + OB_LG);
    float* sA   = reinterpret_cast<float*>(smc + OB_SALL);
    float* attA = reinterpret_cast<float*>(smc + OB_ATT);
    float* wagg = reinterpret_cast<float*>(smc + OB_WAGG);
    float* red  = reinterpret_cast<float*>(smc + OB_RED);
    float* egs  = reinterpret_cast<float*>(smc + OB_EG);
    float* ebs  = reinterpret_cast<float*>(smc + OB_EB);
    float* w41s = reinterpret_cast<float*>(smc + OB_W4S1);

    const float* W4l = W4 + layer*NH*NH;

    const int bi = blockIdx.x;
    const int b  = bi >> 8;
    const int t  = threadIdx.x;
    const int w  = t >> 5;
    const int lane = t & 31;
    const int gid = lane >> 2, tig = lane & 3;

    if (layer == 0) {
        // E load (fp32) + exact logit partials + fp16 SMEM store
        const float4* Eg4 = reinterpret_cast<const float4*>(E0 + (size_t)bi*NN*NH);
        const int q = t >> 4, k4 = t & 15;
        const float4 wv = *reinterpret_cast<const float4*>(g_w4s + 4*k4);
        float part[16];
        #pragma unroll
        for (int c = 0; c < 16; c++) {
            int idx4 = t + 256*c;
            float4 v = Eg4[idx4];
            int j = idx4 >> 4;
            part[c] = v.x*wv.x + v.y*wv.y + v.z*wv.z + v.w*wv.w;
            __half2* dst = reinterpret_cast<__half2*>(Es16 + j*HST + 4*k4);
            dst[0] = __floats2half2_rn(v.x, v.y);
            dst[1] = __floats2half2_rn(v.z, v.w);
        }
        #pragma unroll
        for (int o = 1; o <= 8; o <<= 1)
            #pragma unroll
            for (int c = 0; c < 16; c++)
                part[c] += __shfl_xor_sync(0xffffffffu, part[c], o);
        lgA[q + 16*k4] = part[k4];
        if (t < NH) {
            egs[t]  = eg[t];
            ebs[t]  = eb[t];
            w41s[t] = g_w4s[NH + t];
        }
    } else {
        // E1 load (fp16 direct, 32KB, coalesced uint4)
        const uint4* Eg = reinterpret_cast<const uint4*>(g_E1h + (size_t)bi*NN*NH);
        #pragma unroll
        for (int c = 0; c < 8; c++) {
            int idx = t + 256*c;
            int j = idx >> 3, q = idx & 7;
            *reinterpret_cast<uint4*>(Es16 + j*HST + q*8) = Eg[idx];
        }
    }
    // XJ stage: 32KB coalesced -> SMEM (padded stride, conflict-free epilogue reads)
    {
        const uint4* XJg = reinterpret_cast<const uint4*>(g_XJh + (size_t)b*NN*NH);
        #pragma unroll
        for (int c = 0; c < 8; c++) {
            int idx = t + 256*c;
            int j = idx >> 3, q = idx & 7;
            *reinterpret_cast<uint4*>(XJs + j*HST + q*8) = XJg[idx];
        }
    }
    // W4 layer slice -> fp16 SMEM (row-major [h][k])
    {
        const float2* Wg2 = reinterpret_cast<const float2*>(W4l);
        #pragma unroll
        for (int c = 0; c < 8; c++) {
            int idx2 = t + 256*c;
            int h = idx2 >> 5, k2 = idx2 & 31;
            float2 vw = Wg2[idx2];
            *reinterpret_cast<__half2*>(Wh + h*HST + 2*k2) = __floats2half2_rn(vw.x, vw.y);
        }
    }
    sA[t] = g_S[b*NN + t];
    __syncthreads();

    // --- block softmax over 256 (thread t = row t) ---
    float lg = (layer ? g_LG1[(size_t)bi*NN + t] : lgA[t]) + g_S[bi] + sA[t];
    float m = lg;
    #pragma unroll
    for (int o = 16; o; o >>= 1) m = fmaxf(m, __shfl_xor_sync(0xffffffffu, m, o));
    if (lane == 0) red[w] = m;
    __syncthreads();
    if (t == 0) {
        float mm = red[0];
        for (int q = 1; q < 8; q++) mm = fmaxf(mm, red[q]);
        red[8] = mm;
    }
    __syncthreads();
    m = red[8];
    float ex = expf(lg - m);
    float sum = ex;
    #pragma unroll
    for (int o = 16; o; o >>= 1) sum += __shfl_xor_sync(0xffffffffu, sum, o);
    if (lane == 0) red[w] = sum;
    __syncthreads();
    if (t == 0) {
        float s8 = 0.f;
        for (int q = 0; q < 8; q++) s8 += red[q];
        red[9] = 1.f / s8;
    }
    __syncthreads();
    attA[t] = ex * red[9];
    __syncthreads();

    // --- fp16 tensor GEMM: warp w -> rows [w*32, w*32+32), cols 0..63 ---
    float acc[2][8][4];
    #pragma unroll
    for (int mt = 0; mt < 2; mt++)
        #pragma unroll
        for (int nt = 0; nt < 8; nt++)
            #pragma unroll
            for (int q = 0; q < 4; q++) acc[mt][nt][q] = 0.f;

    const uint32_t* EsU = reinterpret_cast<const uint32_t*>(Es16);
    const uint32_t* WU  = reinterpret_cast<const uint32_t*>(Wh);
    #pragma unroll
    for (int ks = 0; ks < 4; ks++) {
        const int kw = 8*ks + tig;
        uint32_t a[2][4];
        #pragma unroll
        for (int mt = 0; mt < 2; mt++) {
            const int r0 = w*32 + mt*16 + gid;
            a[mt][0] = EsU[r0*36 + kw];
            a[mt][1] = EsU[(r0 + 8)*36 + kw];
            a[mt][2] = EsU[r0*36 + kw + 4];
            a[mt][3] = EsU[(r0 + 8)*36 + kw + 4];
        }
        #pragma unroll
        for (int nt = 0; nt < 8; nt++) {
            const int n = nt*8 + gid;
            uint32_t b0 = WU[n*36 + kw];
            uint32_t b1 = WU[n*36 + kw + 4];
            mma_f16(acc[0][nt], a[0], b0, b1);
            mma_f16(acc[1][nt], a[1], b0, b1);
        }
    }

    // --- fragment epilogue (warp-private rows: no sync needed to reuse Es16) ---
    float aggp[16];
    #pragma unroll
    for (int z = 0; z < 16; z++) aggp[z] = 0.f;
    float* LG1o = g_LG1 + (size_t)bi*NN;

    #pragma unroll
    for (int mt = 0; mt < 2; mt++) {
        const int rA = w*32 + mt*16 + gid;
        const int rB = rA + 8;
        const float aA = attA[rA], aB = attA[rB];
        float s0 = 0.f, q0 = 0.f, s1 = 0.f, q1 = 0.f;
        #pragma unroll
        for (int nt = 0; nt < 8; nt++) {
            float e0 = acc[mt][nt][0] * aA;
            float e1 = acc[mt][nt][1] * aA;
            float e2 = acc[mt][nt][2] * aB;
            float e3 = acc[mt][nt][3] * aB;
            acc[mt][nt][0] = e0; acc[mt][nt][1] = e1;
            acc[mt][nt][2] = e2; acc[mt][nt][3] = e3;
            const int hc = nt*8 + 2*tig;
            float2 xA = __half22float2(*reinterpret_cast<const __half2*>(XJs + rA*HST + hc));
            float2 xB = __half22float2(*reinterpret_cast<const __half2*>(XJs + rB*HST + hc));
            aggp[2*nt]     += e0*xA.x + e2*xB.x;
            aggp[2*nt + 1] += e1*xA.y + e3*xB.y;
            if (layer == 0) {
                s0 += e0 + e1; q0 += e0*e0 + e1*e1;
                s1 += e2 + e3; q1 += e2*e2 + e3*e3;
            }
        }
        if (layer == 0) {
            #pragma unroll
            for (int o = 1; o <= 2; o <<= 1) {
                s0 += __shfl_xor_sync(0xffffffffu, s0, o);
                q0 += __shfl_xor_sync(0xffffffffu, q0, o);
                s1 += __shfl_xor_sync(0xffffffffu, s1, o);
                q1 += __shfl_xor_sync(0xffffffffu, q1, o);
            }
            const float mA = s0 * (1.f/NH);
            const float rsA = rsqrtf(fmaf(q0, 1.f/NH, -mA*mA) + LN_EPS);
            const float mB = s1 * (1.f/NH);
            const float rsB = rsqrtf(fmaf(q1, 1.f/NH, -mB*mB) + LN_EPS);
            float lpA = 0.f, lpB = 0.f;
            #pragma unroll
            for (int nt = 0; nt < 8; nt++) {
                const int hc = nt*8 + 2*tig;
                const float2 g2 = *reinterpret_cast<const float2*>(egs + hc);
                const float2 b2 = *reinterpret_cast<const float2*>(ebs + hc);
                float vA0 = (acc[mt][nt][0] - mA)*rsA*g2.x + b2.x;
                float vA1 = (acc[mt][nt][1] - mA)*rsA*g2.y + b2.y;
                float vB0 = (acc[mt][nt][2] - mB)*rsB*g2.x + b2.x;
                float vB1 = (acc[mt][nt][3] - mB)*rsB*g2.y + b2.y;
                // stage LN'd E1 into own SMEM rows (conflict-free)
                *reinterpret_cast<__half2*>(Es16 + rA*HST + hc) = __floats2half2_rn(vA0, vA1);
                *reinterpret_cast<__half2*>(Es16 + rB*HST + hc) = __floats2half2_rn(vB0, vB1);
                const float2 w2 = *reinterpret_cast<const float2*>(w41s + hc);
                lpA += vA0*w2.x + vA1*w2.y;
                lpB += vB0*w2.x + vB1*w2.y;
            }
            #pragma unroll
            for (int o = 1; o <= 2; o <<= 1) {
                lpA += __shfl_xor_sync(0xffffffffu, lpA, o);
                lpB += __shfl_xor_sync(0xffffffffu, lpB, o);
            }
            if (tig == 0) {
                LG1o[rA] = lpA;
                LG1o[rB] = lpB;
            }
        }
    }

    // --- agg reduce over gid lanes -> wagg ---
    #pragma unroll
    for (int o = 4; o <= 16; o <<= 1)
        #pragma unroll
        for (int z = 0; z < 16; z++)
            aggp[z] += __shfl_xor_sync(0xffffffffu, aggp[z], o);
    if (gid == 0) {
        #pragma unroll
        for (int nt = 0; nt < 8; nt++) {
            wagg[w*64 + nt*8 + 2*tig]     = aggp[2*nt];
            wagg[w*64 + nt*8 + 2*tig + 1] = aggp[2*nt + 1];
        }
    }
    __syncthreads();
    if (t < NH) {
        float s = 0.f;
        #pragma unroll
        for (int q = 0; q < 8; q++) s += wagg[q*64 + t];
        g_AGG[bi*NH + t] = s;
    }
    // --- layer 0: coalesced E1 write-out from staged SMEM ---
    if (layer == 0) {
        uint4* Eo = reinterpret_cast<uint4*>(g_E1h + (size_t)bi*NN*NH);
        #pragma unroll
        for (int c = 0; c < 8; c++) {
            int idx = t + 256*c;
            int j = idx >> 3, q = idx & 7;
            Eo[idx] = *reinterpret_cast<const uint4*>(Es16 + j*HST + q*8);
        }
    }
}

// ---------------- launch ----------------
extern "C" void kernel_launch(void* const* d_in, const int* in_sizes, int n_in,
                              void* d_out, int out_size) {
    const float* X   = (const float*)d_in[0];
    const float* E   = (const float*)d_in[1];
    const float* W3  = (const float*)d_in[2];
    const float* W4  = (const float*)d_in[3];
    const float* W5  = (const float*)d_in[4];
    const float* W6  = (const float*)d_in[5];
    const float* ng  = (const float*)d_in[6];
    const float* nb  = (const float*)d_in[7];
    const float* eg  = (const float*)d_in[8];
    const float* eb  = (const float*)d_in[9];
    const float* hw1 = (const float*)d_in[10];
    const float* hb1 = (const float*)d_in[11];
    const float* hw2 = (const float*)d_in[12];
    const float* hb2 = (const float*)d_in[13];
    float* out = (float*)d_out;

    cudaFuncSetAttribute(k_main, cudaFuncAttributeMaxDynamicSharedMemorySize,
                         SMEM_MAIN_BYTES);

    k_sums<<<1, 128>>>(W3, W4);
    k_xstart<<<NB*NN/8, 512>>>(X, W5, W6);
    k_main<<<NB*NN, 256, SMEM_MAIN_BYTES>>>(E, W4, eg, eb, 0);
    k_xmid<<<NB*NN/8, 512>>>(X, W5, W6, ng, nb);
    k_main<<<NB*NN, 256, SMEM_MAIN_BYTES>>>(E, W4, eg, eb, 1);
    k_final<<<NB*NN/8, 512>>>(ng, nb, hw1, hb1, hw2, hb2, out);
}